// round 2
// baseline (speedup 1.0000x reference)
#include <cuda_runtime.h>
#include <cstdint>

#define N_ROWS 10000
#define DIM    256
#define NB     79            // ceil(10000/128)
#define NPAD   (NB * 128)    // 10112
#define LDOUT  10000

// ---------------- scratch (static device globals: allocation-free) ----------
__device__ float g_x1[NPAD * DIM];
__device__ float g_x2[NPAD * DIM];
__device__ float g_e [NPAD * DIM];

// ---------------- shared GEMM core: C = act(A @ W^T + bias) -----------------
// A: [? x 256] row-major (rows >= mreal read as 0 when GUARD_A)
// W: [rows x 256] row-major; tile of output cols = rows of W
// C: [NPAD x 256] row-major (all tile rows stored; caller guarantees validity)
template<bool RELU, bool GUARD_A>
__device__ __forceinline__ void mlp_gemm_core(const float* __restrict__ A,
                                              const float* __restrict__ W,
                                              const float* __restrict__ bias,
                                              float* __restrict__ C, int mreal)
{
    __shared__ float As[16][128];
    __shared__ float Bs[16][128];
    const int tid  = threadIdx.x;
    const int tx   = tid & 15, ty = tid >> 4;
    const int row0 = ty * 8, col0 = tx * 8;
    const int br = blockIdx.x, bc = blockIdx.y;

    float c[8][8];
#pragma unroll
    for (int i = 0; i < 8; i++)
#pragma unroll
        for (int j = 0; j < 8; j++) c[i][j] = 0.f;

    for (int k0 = 0; k0 < DIM; k0 += 16) {
#pragma unroll
        for (int l = 0; l < 2; l++) {
            int idx = tid * 2 + l;          // 0..511
            int r   = idx >> 2;             // 0..127
            int c4  = (idx & 3) * 4;        // 0,4,8,12
            int arow = br * 128 + r;
            float4 v;
            if (!GUARD_A || arow < mreal)
                v = *reinterpret_cast<const float4*>(&A[(long)arow * DIM + k0 + c4]);
            else
                v = make_float4(0.f, 0.f, 0.f, 0.f);
            As[c4 + 0][r] = v.x; As[c4 + 1][r] = v.y;
            As[c4 + 2][r] = v.z; As[c4 + 3][r] = v.w;

            int wrow = bc * 128 + r;        // always < 256
            float4 w = *reinterpret_cast<const float4*>(&W[(long)wrow * DIM + k0 + c4]);
            Bs[c4 + 0][r] = w.x; Bs[c4 + 1][r] = w.y;
            Bs[c4 + 2][r] = w.z; Bs[c4 + 3][r] = w.w;
        }
        __syncthreads();
#pragma unroll
        for (int k = 0; k < 16; k++) {
            float a[8], b[8];
            *(float4*)&a[0] = *(const float4*)&As[k][row0];
            *(float4*)&a[4] = *(const float4*)&As[k][row0 + 4];
            *(float4*)&b[0] = *(const float4*)&Bs[k][col0];
            *(float4*)&b[4] = *(const float4*)&Bs[k][col0 + 4];
#pragma unroll
            for (int i = 0; i < 8; i++)
#pragma unroll
                for (int j = 0; j < 8; j++)
                    c[i][j] = fmaf(a[i], b[j], c[i][j]);
        }
        __syncthreads();
    }
#pragma unroll
    for (int i = 0; i < 8; i++) {
        int grow = br * 128 + row0 + i;
#pragma unroll
        for (int j = 0; j < 8; j++) {
            int gcol = bc * 128 + col0 + j;
            float v = c[i][j] + bias[gcol];
            if (RELU) v = fmaxf(v, 0.f);
            C[(long)grow * DIM + gcol] = v;
        }
    }
}

__global__ void mlp1_kernel(const float* __restrict__ h,
                            const float* __restrict__ W1,
                            const float* __restrict__ b1)
{
    mlp_gemm_core<true, true>(h, W1, b1, g_x1, N_ROWS);
}

__global__ void mlp2_kernel(const float* __restrict__ W2,
                            const float* __restrict__ b2)
{
    mlp_gemm_core<false, false>(g_x1, W2, b2, g_x2, N_ROWS);
}

// ---------------- row L2-normalize; zero the pad rows -----------------------
__global__ void normalize_kernel()
{
    const int row = blockIdx.x;
    const int tid = threadIdx.x;           // 256 threads == DIM
    float v = g_x2[(long)row * DIM + tid];
    float s = v * v;
#pragma unroll
    for (int off = 16; off > 0; off >>= 1)
        s += __shfl_xor_sync(0xffffffffu, s, off);
    __shared__ float warpsum[8];
    if ((tid & 31) == 0) warpsum[tid >> 5] = s;
    __syncthreads();
    float tot = 0.f;
#pragma unroll
    for (int w = 0; w < 8; w++) tot += warpsum[w];
    float denom = fmaxf(sqrtf(tot), 1e-12f);
    g_e[(long)row * DIM + tid] = (row < N_ROWS) ? v / denom : 0.f;
}

// ---------------- adj = E @ E^T (symmetric: upper-tri blocks + mirror) ------
__global__ void adj_gemm_kernel(float* __restrict__ out)
{
    const int bc = blockIdx.x, br = blockIdx.y;
    if (bc < br) return;                   // lower-triangle blocks mirrored

    __shared__ float As[16][128];
    __shared__ float Bs[16][128];
    __shared__ float Ts[16][132];          // transpose staging (padded)

    const int tid  = threadIdx.x;
    const int tx   = tid & 15, ty = tid >> 4;
    const int row0 = ty * 8, col0 = tx * 8;

    float c[8][8];
#pragma unroll
    for (int i = 0; i < 8; i++)
#pragma unroll
        for (int j = 0; j < 8; j++) c[i][j] = 0.f;

    for (int k0 = 0; k0 < DIM; k0 += 16) {
#pragma unroll
        for (int l = 0; l < 2; l++) {
            int idx = tid * 2 + l;
            int r   = idx >> 2;
            int c4  = (idx & 3) * 4;
            float4 v = *reinterpret_cast<const float4*>(
                &g_e[(long)(br * 128 + r) * DIM + k0 + c4]);
            As[c4 + 0][r] = v.x; As[c4 + 1][r] = v.y;
            As[c4 + 2][r] = v.z; As[c4 + 3][r] = v.w;
            float4 w = *reinterpret_cast<const float4*>(
                &g_e[(long)(bc * 128 + r) * DIM + k0 + c4]);
            Bs[c4 + 0][r] = w.x; Bs[c4 + 1][r] = w.y;
            Bs[c4 + 2][r] = w.z; Bs[c4 + 3][r] = w.w;
        }
        __syncthreads();
#pragma unroll
        for (int k = 0; k < 16; k++) {
            float a[8], b[8];
            *(float4*)&a[0] = *(const float4*)&As[k][row0];
            *(float4*)&a[4] = *(const float4*)&As[k][row0 + 4];
            *(float4*)&b[0] = *(const float4*)&Bs[k][col0];
            *(float4*)&b[4] = *(const float4*)&Bs[k][col0 + 4];
#pragma unroll
            for (int i = 0; i < 8; i++)
#pragma unroll
                for (int j = 0; j < 8; j++)
                    c[i][j] = fmaf(a[i], b[j], c[i][j]);
        }
        __syncthreads();
    }

    // direct store of this tile (upper triangle incl. diagonal)
    const bool colEdge = (bc == NB - 1);
#pragma unroll
    for (int i = 0; i < 8; i++) {
        int grow = br * 128 + row0 + i;
        if (grow >= N_ROWS) continue;      // only when br==NB-1
        long base = (long)grow * LDOUT + bc * 128 + col0;
        if (!colEdge) {
            *reinterpret_cast<float4*>(&out[base])     = *(float4*)&c[i][0];
            *reinterpret_cast<float4*>(&out[base + 4]) = *(float4*)&c[i][4];
        } else {
#pragma unroll
            for (int j = 0; j < 8; j++) {
                int gcol = bc * 128 + col0 + j;
                if (gcol < N_ROWS) out[(long)grow * LDOUT + gcol] = c[i][j];
            }
        }
    }

    // mirrored store (transpose through smem), skip diagonal blocks
    if (br != bc) {
        for (int cc = 0; cc < 8; cc++) {
            if ((tx >> 1) == cc) {
                int lcBase = (tx & 1) * 8;
#pragma unroll
                for (int i = 0; i < 8; i++)
#pragma unroll
                    for (int j = 0; j < 8; j++)
                        Ts[lcBase + j][row0 + i] = c[i][j];
            }
            __syncthreads();
            for (int li = tid; li < 2048; li += 256) {
                int rr = li >> 7, c2 = li & 127;
                int grow = bc * 128 + cc * 16 + rr;
                int gcol = br * 128 + c2;
                if (grow < N_ROWS && gcol < N_ROWS)
                    out[(long)grow * LDOUT + gcol] = Ts[rr][c2];
            }
            __syncthreads();
        }
    }
}

// ---------------- exact per-row top-(k+1) select, in place ------------------
__device__ __forceinline__ unsigned fkey(float f)
{
    unsigned u = __float_as_uint(f);
    return (u & 0x80000000u) ? ~u : (u | 0x80000000u);
}

__global__ void topk_kernel(float* __restrict__ out, const int* __restrict__ kp)
{
    extern __shared__ float vals[];        // 10000 floats = 40000 B
    __shared__ unsigned hist[256];
    __shared__ unsigned sh_prefix, sh_rem, sh_tc;
    __shared__ int sh_cut;
    __shared__ int tieIdx[256];
    __shared__ int tieCnt;

    const int row = blockIdx.x;
    const int tid = threadIdx.x;
    float* rowp = out + (long)row * LDOUT;

    float4*       v4 = reinterpret_cast<float4*>(vals);
    const float4* r4 = reinterpret_cast<const float4*>(rowp);
    for (int i = tid; i < LDOUT / 4; i += 256) v4[i] = r4[i];
    if (tid == 0) { sh_prefix = 0; sh_rem = (unsigned)(kp[0] + 1); tieCnt = 0; }
    __syncthreads();

    unsigned mask = 0;
    for (int shift = 24; shift >= 0; shift -= 8) {
        hist[tid] = 0;
        __syncthreads();
        unsigned pfx = sh_prefix;
        for (int j = tid; j < LDOUT; j += 256) {
            unsigned u = fkey(vals[j]);
            if ((u & mask) == pfx) atomicAdd(&hist[(u >> shift) & 255u], 1u);
        }
        __syncthreads();
        if (tid == 0) {
            unsigned rem = sh_rem, cum = 0;
            for (int b = 255; b >= 0; --b) {
                unsigned hh = hist[b];
                if (cum + hh >= rem) {
                    sh_prefix = pfx | ((unsigned)b << shift);
                    sh_rem    = rem - cum;   // how many ties to keep
                    sh_tc     = hh;          // tie count (exact at last pass)
                    break;
                }
                cum += hh;
            }
        }
        __syncthreads();
        mask |= (0xFFu << shift);
    }
    const unsigned T    = sh_prefix;
    const unsigned need = sh_rem;
    const unsigned tc   = sh_tc;

    int cut;
    if (need >= tc) {
        cut = 0x7fffffff;                  // keep all ties
    } else {
        for (int j = tid; j < LDOUT; j += 256) {
            if (fkey(vals[j]) == T) {
                int p = atomicAdd(&tieCnt, 1);
                if (p < 256) tieIdx[p] = j;
            }
        }
        __syncthreads();
        if (tid == 0) {
            int n = tieCnt;
            int cv = -1;
            if (n <= 256) {
                // need-th smallest tie index (jax top_k is index-stable)
                for (unsigned t = 0; t < need; ++t) {
                    int mi = 0x7fffffff, mp = 0;
                    for (int p = 0; p < n; ++p)
                        if (tieIdx[p] < mi) { mi = tieIdx[p]; mp = p; }
                    cv = mi; tieIdx[mp] = 0x7fffffff;
                }
            } else {
                unsigned cnt = 0;
                for (int j = 0; j < LDOUT; ++j)
                    if (fkey(vals[j]) == T) { if (++cnt == need) { cv = j; break; } }
            }
            sh_cut = cv;
        }
        __syncthreads();
        cut = sh_cut;
    }

    for (int i = tid; i < LDOUT / 4; i += 256) {
        float4 v = v4[i];
        int j0 = i * 4;
        float* pv = &v.x;
#pragma unroll
        for (int q = 0; q < 4; ++q) {
            unsigned u = fkey(pv[q]);
            bool keep = (u > T) || (u == T && (j0 + q) <= cut);
            pv[q] = keep ? fmaxf(pv[q], 0.f) : 0.f;
        }
        reinterpret_cast<float4*>(rowp)[i] = v;
    }
}

// ---------------- launch ----------------------------------------------------
extern "C" void kernel_launch(void* const* d_in, const int* in_sizes, int n_in,
                              void* d_out, int out_size)
{
    const float* h  = (const float*)d_in[0];
    const float* W1 = (const float*)d_in[1];
    const float* b1 = (const float*)d_in[2];
    const float* W2 = (const float*)d_in[3];
    const float* b2 = (const float*)d_in[4];
    const int*   kp = (const int*)  d_in[5];
    float* out = (float*)d_out;

    mlp1_kernel<<<dim3(NB, 2), 256>>>(h, W1, b1);
    mlp2_kernel<<<dim3(NB, 2), 256>>>(W2, b2);
    normalize_kernel<<<NPAD, 256>>>();
    adj_gemm_kernel<<<dim3(NB, NB), 256>>>(out);
    topk_kernel<<<N_ROWS, 256, LDOUT * sizeof(float)>>>(out, kp);
}

// round 3
// speedup vs baseline: 1.1126x; 1.1126x over previous
#include <cuda_runtime.h>
#include <cstdint>

#define N_ROWS 10000
#define DIM    256
#define NB     79            // ceil(10000/128)
#define NPAD   (NB * 128)    // 10112
#define LDOUT  10000

// ---------------- scratch (static device globals: allocation-free) ----------
__device__ float g_x1[NPAD * DIM];
__device__ float g_x2[NPAD * DIM];
__device__ float g_e [NPAD * DIM];

// ---------------- shared GEMM core: C = act(A @ W^T + bias) -----------------
template<bool RELU, bool GUARD_A>
__device__ __forceinline__ void mlp_gemm_core(const float* __restrict__ A,
                                              const float* __restrict__ W,
                                              const float* __restrict__ bias,
                                              float* __restrict__ C, int mreal)
{
    __shared__ float As[16][128];
    __shared__ float Bs[16][128];
    const int tid  = threadIdx.x;
    const int tx   = tid & 15, ty = tid >> 4;
    const int row0 = ty * 8, col0 = tx * 8;
    const int br = blockIdx.x, bc = blockIdx.y;

    float c[8][8];
#pragma unroll
    for (int i = 0; i < 8; i++)
#pragma unroll
        for (int j = 0; j < 8; j++) c[i][j] = 0.f;

    for (int k0 = 0; k0 < DIM; k0 += 16) {
#pragma unroll
        for (int l = 0; l < 2; l++) {
            int idx = tid * 2 + l;          // 0..511
            int r   = idx >> 2;             // 0..127
            int c4  = (idx & 3) * 4;        // 0,4,8,12
            int arow = br * 128 + r;
            float4 v;
            if (!GUARD_A || arow < mreal)
                v = *reinterpret_cast<const float4*>(&A[(long)arow * DIM + k0 + c4]);
            else
                v = make_float4(0.f, 0.f, 0.f, 0.f);
            As[c4 + 0][r] = v.x; As[c4 + 1][r] = v.y;
            As[c4 + 2][r] = v.z; As[c4 + 3][r] = v.w;

            int wrow = bc * 128 + r;        // always < 256
            float4 w = *reinterpret_cast<const float4*>(&W[(long)wrow * DIM + k0 + c4]);
            Bs[c4 + 0][r] = w.x; Bs[c4 + 1][r] = w.y;
            Bs[c4 + 2][r] = w.z; Bs[c4 + 3][r] = w.w;
        }
        __syncthreads();
#pragma unroll
        for (int k = 0; k < 16; k++) {
            float a[8], b[8];
            *(float4*)&a[0] = *(const float4*)&As[k][row0];
            *(float4*)&a[4] = *(const float4*)&As[k][row0 + 4];
            *(float4*)&b[0] = *(const float4*)&Bs[k][col0];
            *(float4*)&b[4] = *(const float4*)&Bs[k][col0 + 4];
#pragma unroll
            for (int i = 0; i < 8; i++)
#pragma unroll
                for (int j = 0; j < 8; j++)
                    c[i][j] = fmaf(a[i], b[j], c[i][j]);
        }
        __syncthreads();
    }
#pragma unroll
    for (int i = 0; i < 8; i++) {
        int grow = br * 128 + row0 + i;
#pragma unroll
        for (int j = 0; j < 8; j++) {
            int gcol = bc * 128 + col0 + j;
            float v = c[i][j] + bias[gcol];
            if (RELU) v = fmaxf(v, 0.f);
            C[(long)grow * DIM + gcol] = v;
        }
    }
}

__global__ void mlp1_kernel(const float* __restrict__ h,
                            const float* __restrict__ W1,
                            const float* __restrict__ b1)
{
    mlp_gemm_core<true, true>(h, W1, b1, g_x1, N_ROWS);
}

__global__ void mlp2_kernel(const float* __restrict__ W2,
                            const float* __restrict__ b2)
{
    mlp_gemm_core<false, false>(g_x1, W2, b2, g_x2, N_ROWS);
}

// ---------------- row L2-normalize; zero the pad rows -----------------------
__global__ void normalize_kernel()
{
    const int row = blockIdx.x;
    const int tid = threadIdx.x;           // 256 threads == DIM
    float v = g_x2[(long)row * DIM + tid];
    float s = v * v;
#pragma unroll
    for (int off = 16; off > 0; off >>= 1)
        s += __shfl_xor_sync(0xffffffffu, s, off);
    __shared__ float warpsum[8];
    if ((tid & 31) == 0) warpsum[tid >> 5] = s;
    __syncthreads();
    float tot = 0.f;
#pragma unroll
    for (int w = 0; w < 8; w++) tot += warpsum[w];
    float denom = fmaxf(sqrtf(tot), 1e-12f);
    g_e[(long)row * DIM + tid] = (row < N_ROWS) ? v / denom : 0.f;
}

// ---------------- adj = E @ E^T (symmetric, double-buffered) ----------------
// Upper-triangle blocks computed; mirror written directly from registers.
// NOTE: when br != bc we have br <= NB-2, so mirror columns (br tile) are
// always < N_ROWS -> unguarded float4 stores. Mirror rows (bc tile) need a
// guard only when bc == NB-1.
__global__ void __launch_bounds__(256, 2) adj_gemm_kernel(float* __restrict__ out)
{
    const int bc = blockIdx.x, br = blockIdx.y;
    if (bc < br) return;

    __shared__ float As[2][16][128];
    __shared__ float Bs[2][16][128];

    const int tid  = threadIdx.x;
    const int tx   = tid & 15, ty = tid >> 4;
    const int row0 = ty * 8, col0 = tx * 8;

    // loader lanes: two float4 per array per tile
    const int i0 = tid * 2,     i1 = tid * 2 + 1;
    const int r0 = i0 >> 2,     r1 = i1 >> 2;
    const int c40 = (i0 & 3)*4, c41 = (i1 & 3)*4;
    const float* Abase = &g_e[(long)(br * 128) * DIM];
    const float* Bbase = &g_e[(long)(bc * 128) * DIM];

    float c[8][8];
#pragma unroll
    for (int i = 0; i < 8; i++)
#pragma unroll
        for (int j = 0; j < 8; j++) c[i][j] = 0.f;

    // preload k0 = 0 into buffer 0
    {
        float4 a0 = *(const float4*)&Abase[(long)r0 * DIM + c40];
        float4 a1 = *(const float4*)&Abase[(long)r1 * DIM + c41];
        float4 b0 = *(const float4*)&Bbase[(long)r0 * DIM + c40];
        float4 b1 = *(const float4*)&Bbase[(long)r1 * DIM + c41];
        As[0][c40+0][r0]=a0.x; As[0][c40+1][r0]=a0.y; As[0][c40+2][r0]=a0.z; As[0][c40+3][r0]=a0.w;
        As[0][c41+0][r1]=a1.x; As[0][c41+1][r1]=a1.y; As[0][c41+2][r1]=a1.z; As[0][c41+3][r1]=a1.w;
        Bs[0][c40+0][r0]=b0.x; Bs[0][c40+1][r0]=b0.y; Bs[0][c40+2][r0]=b0.z; Bs[0][c40+3][r0]=b0.w;
        Bs[0][c41+0][r1]=b1.x; Bs[0][c41+1][r1]=b1.y; Bs[0][c41+2][r1]=b1.z; Bs[0][c41+3][r1]=b1.w;
    }
    __syncthreads();

    int p = 0;
#pragma unroll
    for (int k0 = 0; k0 < DIM; k0 += 16) {
        float4 a0, a1, b0, b1;
        const bool more = (k0 + 16 < DIM);
        if (more) {
            a0 = *(const float4*)&Abase[(long)r0 * DIM + k0 + 16 + c40];
            a1 = *(const float4*)&Abase[(long)r1 * DIM + k0 + 16 + c41];
            b0 = *(const float4*)&Bbase[(long)r0 * DIM + k0 + 16 + c40];
            b1 = *(const float4*)&Bbase[(long)r1 * DIM + k0 + 16 + c41];
        }
#pragma unroll
        for (int k = 0; k < 16; k++) {
            float a[8], b[8];
            *(float4*)&a[0] = *(const float4*)&As[p][k][row0];
            *(float4*)&a[4] = *(const float4*)&As[p][k][row0 + 4];
            *(float4*)&b[0] = *(const float4*)&Bs[p][k][col0];
            *(float4*)&b[4] = *(const float4*)&Bs[p][k][col0 + 4];
#pragma unroll
            for (int i = 0; i < 8; i++)
#pragma unroll
                for (int j = 0; j < 8; j++)
                    c[i][j] = fmaf(a[i], b[j], c[i][j]);
        }
        if (more) {
            int q = p ^ 1;
            As[q][c40+0][r0]=a0.x; As[q][c40+1][r0]=a0.y; As[q][c40+2][r0]=a0.z; As[q][c40+3][r0]=a0.w;
            As[q][c41+0][r1]=a1.x; As[q][c41+1][r1]=a1.y; As[q][c41+2][r1]=a1.z; As[q][c41+3][r1]=a1.w;
            Bs[q][c40+0][r0]=b0.x; Bs[q][c40+1][r0]=b0.y; Bs[q][c40+2][r0]=b0.z; Bs[q][c40+3][r0]=b0.w;
            Bs[q][c41+0][r1]=b1.x; Bs[q][c41+1][r1]=b1.y; Bs[q][c41+2][r1]=b1.z; Bs[q][c41+3][r1]=b1.w;
        }
        __syncthreads();
        p ^= 1;
    }

    // direct store of upper tile
    const bool colEdge = (bc == NB - 1);
#pragma unroll
    for (int i = 0; i < 8; i++) {
        int grow = br * 128 + row0 + i;
        if (grow >= N_ROWS) continue;          // only when br==NB-1
        long base = (long)grow * LDOUT + bc * 128 + col0;
        if (!colEdge) {
            *reinterpret_cast<float4*>(&out[base])     = *(float4*)&c[i][0];
            *reinterpret_cast<float4*>(&out[base + 4]) = *(float4*)&c[i][4];
        } else {
#pragma unroll
            for (int j = 0; j < 8; j++) {
                int gcol = bc * 128 + col0 + j;
                if (gcol < N_ROWS) out[(long)grow * LDOUT + gcol] = c[i][j];
            }
        }
    }

    // mirrored store directly from registers
    if (br != bc) {
#pragma unroll
        for (int j = 0; j < 8; j++) {
            int grow = bc * 128 + col0 + j;    // mirror row
            if (grow >= N_ROWS) continue;      // only when bc==NB-1
            long base = (long)grow * LDOUT + br * 128 + row0;   // cols always < N_ROWS
            float4 v0 = make_float4(c[0][j], c[1][j], c[2][j], c[3][j]);
            float4 v1 = make_float4(c[4][j], c[5][j], c[6][j], c[7][j]);
            *reinterpret_cast<float4*>(&out[base])     = v0;
            *reinterpret_cast<float4*>(&out[base + 4]) = v1;
        }
    }
}

// ---------------- exact per-row top-(k+1), 12-bit radix + candidate rank ----
__device__ __forceinline__ unsigned fkey(float f)
{
    unsigned u = __float_as_uint(f);
    return (u & 0x80000000u) ? ~u : (u | 0x80000000u);
}

#define NCAND 2048

__global__ void topk_kernel(float* __restrict__ out, const int* __restrict__ kp)
{
    __shared__ unsigned hist[4096];
    __shared__ unsigned chunkSum[256];
    __shared__ unsigned candKey[NCAND];
    __shared__ int      candIdx[NCAND];
    __shared__ int      candCnt;
    __shared__ unsigned sh_bin, sh_rem;
    __shared__ unsigned sh_T;
    __shared__ int      sh_cut;

    const int row = blockIdx.x;
    const int tid = threadIdx.x;
    float* rowp = out + (long)row * LDOUT;
    const float4* r4 = reinterpret_cast<const float4*>(rowp);

    for (int i = tid; i < 4096; i += 256) hist[i] = 0;
    if (tid == 0) candCnt = 0;
    __syncthreads();

    // pass 1: 12-bit histogram of monotonic keys
    for (int i = tid; i < LDOUT / 4; i += 256) {
        float4 v = r4[i];
        atomicAdd(&hist[fkey(v.x) >> 20], 1u);
        atomicAdd(&hist[fkey(v.y) >> 20], 1u);
        atomicAdd(&hist[fkey(v.z) >> 20], 1u);
        atomicAdd(&hist[fkey(v.w) >> 20], 1u);
    }
    __syncthreads();

    // suffix scan: chunk sums then serial pick
    {
        unsigned s = 0;
#pragma unroll
        for (int b = 0; b < 16; b++) s += hist[tid * 16 + b];
        chunkSum[tid] = s;
    }
    __syncthreads();
    if (tid == 0) {
        unsigned K1 = (unsigned)(kp[0] + 1);
        unsigned cum = 0;
        for (int t = 255; t >= 0; --t) {
            if (cum + chunkSum[t] >= K1) {
                for (int b = t * 16 + 15; b >= t * 16; --b) {
                    unsigned h = hist[b];
                    if (cum + h >= K1) { sh_bin = (unsigned)b; sh_rem = K1 - cum; break; }
                    cum += h;
                }
                break;
            }
            cum += chunkSum[t];
        }
    }
    __syncthreads();
    const unsigned bin = sh_bin;
    const unsigned rem = sh_rem;

    // pass 2: collect candidates in threshold bin (L2-resident re-read)
    for (int i = tid; i < LDOUT / 4; i += 256) {
        float4 v = r4[i];
        const float* pv = &v.x;
#pragma unroll
        for (int q = 0; q < 4; ++q) {
            unsigned u = fkey(pv[q]);
            if ((u >> 20) == bin) {
                int p = atomicAdd(&candCnt, 1);
                if (p < NCAND) { candKey[p] = u; candIdx[p] = i * 4 + q; }
            }
        }
    }
    __syncthreads();
    const int n = candCnt < NCAND ? candCnt : NCAND;

    // rank candidates: (key desc, idx asc); the rank==(rem-1) one is the cut
    for (int cI = tid; cI < n; cI += 256) {
        unsigned k = candKey[cI];
        int id = candIdx[cI];
        unsigned rank = 0;
        for (int o = 0; o < n; ++o) {
            unsigned ko = candKey[o];
            rank += (ko > k) || (ko == k && candIdx[o] < id);
        }
        if (rank == rem - 1) { sh_T = k; sh_cut = id; }
    }
    __syncthreads();
    const unsigned T = sh_T;
    const int cut = sh_cut;

    // pass 3: rewrite row (mask + relu)
    for (int i = tid; i < LDOUT / 4; i += 256) {
        float4 v = r4[i];
        float* pv = &v.x;
        int j0 = i * 4;
#pragma unroll
        for (int q = 0; q < 4; ++q) {
            unsigned u = fkey(pv[q]);
            bool keep = (u > T) || (u == T && (j0 + q) <= cut);
            pv[q] = keep ? fmaxf(pv[q], 0.f) : 0.f;
        }
        reinterpret_cast<float4*>(rowp)[i] = v;
    }
}

// ---------------- launch ----------------------------------------------------
extern "C" void kernel_launch(void* const* d_in, const int* in_sizes, int n_in,
                              void* d_out, int out_size)
{
    const float* h  = (const float*)d_in[0];
    const float* W1 = (const float*)d_in[1];
    const float* b1 = (const float*)d_in[2];
    const float* W2 = (const float*)d_in[3];
    const float* b2 = (const float*)d_in[4];
    const int*   kp = (const int*)  d_in[5];
    float* out = (float*)d_out;

    mlp1_kernel<<<dim3(NB, 2), 256>>>(h, W1, b1);
    mlp2_kernel<<<dim3(NB, 2), 256>>>(W2, b2);
    normalize_kernel<<<NPAD, 256>>>();
    adj_gemm_kernel<<<dim3(NB, NB), 256>>>(out);
    topk_kernel<<<N_ROWS, 256>>>(out, kp);
}

// round 6
// speedup vs baseline: 1.3291x; 1.1946x over previous
#include <cuda_runtime.h>
#include <cuda_bf16.h>
#include <cstdint>

#define N_ROWS 10000
#define DIM    256
#define NB     79            // ceil(10000/128)
#define NPAD   (NB * 128)    // 10112
#define LDOUT  10000
#define CAND_MAX 1024
#define DELTA  5e-4f

// ---------------- scratch (static device globals: allocation-free) ----------
__device__ float g_x1[NPAD * DIM];
__device__ float g_e [NPAD * DIM];
__device__ __nv_bfloat16 g_ehi[NPAD * DIM];
__device__ __nv_bfloat16 g_elo[NPAD * DIM];
__device__ int g_cand [N_ROWS * CAND_MAX];
__device__ int g_candn[N_ROWS];

// ================= helpers =================
__device__ __forceinline__ uint32_t smem_u32(const void* p) {
    uint32_t a;
    asm("{ .reg .u64 t; cvta.to.shared.u64 t, %1; cvt.u32.u64 %0, t; }" : "=r"(a) : "l"(p));
    return a;
}
__device__ __forceinline__ void cp16(uint32_t dst, const void* src) {
    asm volatile("cp.async.cg.shared.global [%0], [%1], 16;" :: "r"(dst), "l"(src));
}
#define CP_COMMIT() asm volatile("cp.async.commit_group;")
#define CP_WAIT0()  asm volatile("cp.async.wait_group 0;")

__device__ __forceinline__ void ldm_x4(uint32_t& r0, uint32_t& r1, uint32_t& r2, uint32_t& r3,
                                       uint32_t addr) {
    asm volatile("ldmatrix.sync.aligned.m8n8.x4.shared.b16 {%0,%1,%2,%3}, [%4];"
                 : "=r"(r0), "=r"(r1), "=r"(r2), "=r"(r3) : "r"(addr));
}
__device__ __forceinline__ void ldm_x2(uint32_t& r0, uint32_t& r1, uint32_t addr) {
    asm volatile("ldmatrix.sync.aligned.m8n8.x2.shared.b16 {%0,%1}, [%2];"
                 : "=r"(r0), "=r"(r1) : "r"(addr));
}
__device__ __forceinline__ void mma_bf16(float* c, const uint32_t* a, const uint32_t* b) {
    asm volatile("mma.sync.aligned.m16n8k16.row.col.f32.bf16.bf16.f32 "
                 "{%0,%1,%2,%3}, {%4,%5,%6,%7}, {%8,%9}, {%0,%1,%2,%3};"
                 : "+f"(c[0]), "+f"(c[1]), "+f"(c[2]), "+f"(c[3])
                 : "r"(a[0]), "r"(a[1]), "r"(a[2]), "r"(a[3]), "r"(b[0]), "r"(b[1]));
}

// ---------------- shared GEMM core: C = act(A @ W^T + bias) -----------------
template<bool RELU, bool GUARD_A>
__device__ __forceinline__ void mlp_gemm_core(const float* __restrict__ A,
                                              const float* __restrict__ W,
                                              const float* __restrict__ bias,
                                              float* __restrict__ C, int mreal)
{
    __shared__ float As[16][128];
    __shared__ float Bs[16][128];
    const int tid  = threadIdx.x;
    const int tx   = tid & 15, ty = tid >> 4;
    const int row0 = ty * 8, col0 = tx * 8;
    const int br = blockIdx.x, bc = blockIdx.y;

    float c[8][8];
#pragma unroll
    for (int i = 0; i < 8; i++)
#pragma unroll
        for (int j = 0; j < 8; j++) c[i][j] = 0.f;

    for (int k0 = 0; k0 < DIM; k0 += 16) {
#pragma unroll
        for (int l = 0; l < 2; l++) {
            int idx = tid * 2 + l;
            int r   = idx >> 2;
            int c4  = (idx & 3) * 4;
            int arow = br * 128 + r;
            float4 v;
            if (!GUARD_A || arow < mreal)
                v = *reinterpret_cast<const float4*>(&A[(long)arow * DIM + k0 + c4]);
            else
                v = make_float4(0.f, 0.f, 0.f, 0.f);
            As[c4 + 0][r] = v.x; As[c4 + 1][r] = v.y;
            As[c4 + 2][r] = v.z; As[c4 + 3][r] = v.w;
            int wrow = bc * 128 + r;
            float4 w = *reinterpret_cast<const float4*>(&W[(long)wrow * DIM + k0 + c4]);
            Bs[c4 + 0][r] = w.x; Bs[c4 + 1][r] = w.y;
            Bs[c4 + 2][r] = w.z; Bs[c4 + 3][r] = w.w;
        }
        __syncthreads();
#pragma unroll
        for (int k = 0; k < 16; k++) {
            float a[8], b[8];
            *(float4*)&a[0] = *(const float4*)&As[k][row0];
            *(float4*)&a[4] = *(const float4*)&As[k][row0 + 4];
            *(float4*)&b[0] = *(const float4*)&Bs[k][col0];
            *(float4*)&b[4] = *(const float4*)&Bs[k][col0 + 4];
#pragma unroll
            for (int i = 0; i < 8; i++)
#pragma unroll
                for (int j = 0; j < 8; j++)
                    c[i][j] = fmaf(a[i], b[j], c[i][j]);
        }
        __syncthreads();
    }
#pragma unroll
    for (int i = 0; i < 8; i++) {
        int grow = br * 128 + row0 + i;
#pragma unroll
        for (int j = 0; j < 8; j++) {
            int gcol = bc * 128 + col0 + j;
            float v = c[i][j] + bias[gcol];
            if (RELU) v = fmaxf(v, 0.f);
            C[(long)grow * DIM + gcol] = v;
        }
    }
}

__global__ void mlp1_kernel(const float* __restrict__ h,
                            const float* __restrict__ W1,
                            const float* __restrict__ b1)
{
    mlp_gemm_core<true, true>(h, W1, b1, g_x1, N_ROWS);
}

__global__ void mlp2_kernel(const float* __restrict__ W2,
                            const float* __restrict__ b2)
{
    mlp_gemm_core<false, false>(g_x1, W2, b2, g_e, N_ROWS);
}

// -------- row L2-normalize; emit fp32 e and bf16 hi/lo split; zero pads -----
__global__ void normalize_kernel()
{
    const int row = blockIdx.x;
    const int tid = threadIdx.x;           // 256 == DIM
    float v = g_e[(long)row * DIM + tid];
    float s = v * v;
#pragma unroll
    for (int off = 16; off > 0; off >>= 1)
        s += __shfl_xor_sync(0xffffffffu, s, off);
    __shared__ float warpsum[8];
    if ((tid & 31) == 0) warpsum[tid >> 5] = s;
    __syncthreads();
    float tot = 0.f;
#pragma unroll
    for (int w = 0; w < 8; w++) tot += warpsum[w];
    float denom = fmaxf(sqrtf(tot), 1e-12f);
    float e = (row < N_ROWS) ? v / denom : 0.f;
    g_e[(long)row * DIM + tid] = e;
    __nv_bfloat16 hi = __float2bfloat16(e);
    __nv_bfloat16 lo = __float2bfloat16(e - __bfloat162float(hi));
    g_ehi[(long)row * DIM + tid] = hi;
    g_elo[(long)row * DIM + tid] = lo;
}

// ---------------- approx adj via mma.sync bf16 (hi/lo split, symmetric) -----
#define KT    32
#define APAD  40                         // row pitch in bf16 elems (80 B)
#define MATB  (128 * APAD * 2)           // 10240 B per matrix buffer
#define BUFB  (2 * MATB)                 // A+B per buffer
#define NCHUNK 24                        // 768 / 32

__global__ void __launch_bounds__(256, 2) adj_hmma_kernel(float* __restrict__ out)
{
    const int bc = blockIdx.x, br = blockIdx.y;
    if (bc < br) return;

    __shared__ __align__(16) char smem_raw[2 * BUFB];   // 40960 B
    const uint32_t sb = smem_u32(smem_raw);

    const int tid  = threadIdx.x;
    const int wid  = tid >> 5, lane = tid & 31;
    const int warp_m = wid >> 2, warp_n = wid & 3;      // 2 x 4 warp grid

    float acc[4][4][4];
#pragma unroll
    for (int mi = 0; mi < 4; mi++)
#pragma unroll
        for (int ni = 0; ni < 4; ni++)
#pragma unroll
            for (int q = 0; q < 4; q++) acc[mi][ni][q] = 0.f;

    const size_t aBase = (size_t)(br * 128) * DIM;
    const size_t bBase = (size_t)(bc * 128) * DIM;

    const int u0r = tid >> 2,         u0c = (tid & 3) * 16;
    const int u1r = (tid + 256) >> 2, u1c = u0c;

    auto issue = [&](int chunk, int buf) {
        const int term = chunk >> 3;                    // 0:hi*hi 1:lo*hi 2:hi*lo
        const int kk   = (chunk & 7) * KT;
        const __nv_bfloat16* srcA = (term == 1) ? g_elo : g_ehi;
        const __nv_bfloat16* srcB = (term == 2) ? g_elo : g_ehi;
        const char* gA = (const char*)(srcA + aBase + kk);
        const char* gB = (const char*)(srcB + bBase + kk);
        uint32_t dA = sb + buf * BUFB;
        uint32_t dB = dA + MATB;
        cp16(dA + u0r * 80 + u0c, gA + (size_t)u0r * (DIM * 2) + u0c);
        cp16(dA + u1r * 80 + u1c, gA + (size_t)u1r * (DIM * 2) + u1c);
        cp16(dB + u0r * 80 + u0c, gB + (size_t)u0r * (DIM * 2) + u0c);
        cp16(dB + u1r * 80 + u1c, gB + (size_t)u1r * (DIM * 2) + u1c);
    };

    const uint32_t aAddr0 = sb + ((warp_m * 64 + (lane & 15)) * APAD) * 2 + (lane >> 4) * 16;
    const uint32_t bAddr0 = sb + MATB + ((warp_n * 32 + (lane & 7)) * APAD) * 2
                               + ((lane >> 3) & 1) * 16;

    issue(0, 0); CP_COMMIT(); CP_WAIT0(); __syncthreads();

    for (int c = 0; c < NCHUNK; ++c) {
        const int buf = c & 1;
        if (c + 1 < NCHUNK) { issue(c + 1, buf ^ 1); CP_COMMIT(); }

        const uint32_t aB = aAddr0 + buf * BUFB;
        const uint32_t bB = bAddr0 + buf * BUFB;
#pragma unroll
        for (int ks = 0; ks < 2; ++ks) {
            uint32_t afr[4][4], bfr[4][2];
#pragma unroll
            for (int mi = 0; mi < 4; mi++)
                ldm_x4(afr[mi][0], afr[mi][1], afr[mi][2], afr[mi][3],
                       aB + mi * (16 * APAD * 2) + ks * 32);
#pragma unroll
            for (int ni = 0; ni < 4; ni++)
                ldm_x2(bfr[ni][0], bfr[ni][1],
                       bB + ni * (8 * APAD * 2) + ks * 32);
#pragma unroll
            for (int mi = 0; mi < 4; mi++)
#pragma unroll
                for (int ni = 0; ni < 4; ni++)
                    mma_bf16(acc[mi][ni], afr[mi], bfr[ni]);
        }
        if (c + 1 < NCHUNK) { CP_WAIT0(); __syncthreads(); }
    }

    // ---- direct store of upper tile ----
#pragma unroll
    for (int mi = 0; mi < 4; mi++) {
        const int r0 = br * 128 + warp_m * 64 + mi * 16 + (lane >> 2);
#pragma unroll
        for (int ni = 0; ni < 4; ni++) {
            const int gc = bc * 128 + warp_n * 32 + ni * 8 + (lane & 3) * 2;
            if (gc < N_ROWS) {
                if (r0 < N_ROWS)
                    *reinterpret_cast<float2*>(&out[(long)r0 * LDOUT + gc]) =
                        make_float2(acc[mi][ni][0], acc[mi][ni][1]);
                if (r0 + 8 < N_ROWS)
                    *reinterpret_cast<float2*>(&out[(long)(r0 + 8) * LDOUT + gc]) =
                        make_float2(acc[mi][ni][2], acc[mi][ni][3]);
            }
        }
    }

    // ---- mirrored store via smem transpose (skip diagonal) ----
    if (br != bc) {
        float* Tf = reinterpret_cast<float*>(smem_raw);   // [128 cols][68 rows]
#pragma unroll
        for (int h = 0; h < 2; ++h) {
            __syncthreads();
            if (warp_m == h) {
#pragma unroll
                for (int mi = 0; mi < 4; mi++) {
                    const int rl = mi * 16 + (lane >> 2);
#pragma unroll
                    for (int ni = 0; ni < 4; ni++) {
                        const int cl = warp_n * 32 + ni * 8 + (lane & 3) * 2;
                        Tf[cl * 68 + rl]           = acc[mi][ni][0];
                        Tf[(cl + 1) * 68 + rl]     = acc[mi][ni][1];
                        Tf[cl * 68 + rl + 8]       = acc[mi][ni][2];
                        Tf[(cl + 1) * 68 + rl + 8] = acc[mi][ni][3];
                    }
                }
            }
            __syncthreads();
#pragma unroll
            for (int p = 0; p < 8; ++p) {
                const int idx = tid + p * 256;
                const int i = idx >> 4;
                const int j = idx & 15;
                const int grow2 = bc * 128 + i;
                if (grow2 < N_ROWS) {
                    long base = (long)grow2 * LDOUT + br * 128 + h * 64 + j * 4;
                    float4 v;
                    v.x = Tf[i * 68 + j * 4 + 0];
                    v.y = Tf[i * 68 + j * 4 + 1];
                    v.z = Tf[i * 68 + j * 4 + 2];
                    v.w = Tf[i * 68 + j * 4 + 3];
                    *reinterpret_cast<float4*>(&out[base]) = v;
                }
            }
        }
    }
}

// -------- candidate selection: 2-level 12-bit radix + value margin ----------
__device__ __forceinline__ unsigned fkey(float f)
{
    unsigned u = __float_as_uint(f);
    return (u & 0x80000000u) ? ~u : (u | 0x80000000u);
}
__device__ __forceinline__ float kinv(unsigned key)
{
    unsigned u = (key & 0x80000000u) ? (key & 0x7fffffffu) : ~key;
    return __uint_as_float(u);
}

__global__ void cand_kernel(const float* __restrict__ out, const int* __restrict__ kp)
{
    __shared__ unsigned hist[4096];
    __shared__ unsigned chunkSum[256];
    __shared__ int candCnt;
    __shared__ unsigned sh_b1, sh_r1, sh_b2;

    const int row = blockIdx.x;
    const int tid = threadIdx.x;
    const float4* r4 = reinterpret_cast<const float4*>(out + (long)row * LDOUT);
    const unsigned K1 = (unsigned)(kp[0] + 1);

    for (int i = tid; i < 4096; i += 256) hist[i] = 0;
    if (tid == 0) candCnt = 0;
    __syncthreads();

    // ---- pass 1: top-12-bit histogram ----
    for (int i = tid; i < LDOUT / 4; i += 256) {
        float4 v = r4[i];
        atomicAdd(&hist[fkey(v.x) >> 20], 1u);
        atomicAdd(&hist[fkey(v.y) >> 20], 1u);
        atomicAdd(&hist[fkey(v.z) >> 20], 1u);
        atomicAdd(&hist[fkey(v.w) >> 20], 1u);
    }
    __syncthreads();
    {
        unsigned s = 0;
#pragma unroll
        for (int b = 0; b < 16; b++) s += hist[tid * 16 + b];
        chunkSum[tid] = s;
    }
    __syncthreads();
    if (tid == 0) {
        unsigned cum = 0;
        for (int t = 255; t >= 0; --t) {
            if (cum + chunkSum[t] >= K1) {
                for (int b = t * 16 + 15; b >= t * 16; --b) {
                    unsigned hh = hist[b];
                    if (cum + hh >= K1) { sh_b1 = (unsigned)b; sh_r1 = K1 - cum; break; }
                    cum += hh;
                }
                break;
            }
            cum += chunkSum[t];
        }
    }
    __syncthreads();
    const unsigned b1 = sh_b1, r1 = sh_r1;

    // ---- pass 2: refine next 12 bits inside bin b1 ----
    for (int i = tid; i < 4096; i += 256) hist[i] = 0;
    __syncthreads();
    for (int i = tid; i < LDOUT / 4; i += 256) {
        float4 v = r4[i];
        const float* pv = &v.x;
#pragma unroll
        for (int q = 0; q < 4; ++q) {
            unsigned u = fkey(pv[q]);
            if ((u >> 20) == b1) atomicAdd(&hist[(u >> 8) & 0xFFFu], 1u);
        }
    }
    __syncthreads();
    {
        unsigned s = 0;
#pragma unroll
        for (int b = 0; b < 16; b++) s += hist[tid * 16 + b];
        chunkSum[tid] = s;
    }
    __syncthreads();
    if (tid == 0) {
        unsigned cum = 0;
        sh_b2 = 0;
        for (int t = 255; t >= 0; --t) {
            if (cum + chunkSum[t] >= r1) {
                for (int b = t * 16 + 15; b >= t * 16; --b) {
                    unsigned hh = hist[b];
                    if (cum + hh >= r1) { sh_b2 = (unsigned)b; break; }
                    cum += hh;
                }
                break;
            }
            cum += chunkSum[t];
        }
    }
    __syncthreads();

    // threshold: sub-bin floor value minus safety margin
    const unsigned F = (b1 << 20) | (sh_b2 << 8);
    const unsigned Tm = fkey(kinv(F) - DELTA);

    // ---- pass 3: collect candidates with key >= Tm ----
    for (int i = tid; i < LDOUT / 4; i += 256) {
        float4 v = r4[i];
        const float* pv = &v.x;
#pragma unroll
        for (int q = 0; q < 4; ++q) {
            if (fkey(pv[q]) >= Tm) {
                int p = atomicAdd(&candCnt, 1);
                if (p < CAND_MAX) g_cand[row * CAND_MAX + p] = i * 4 + q;
            }
        }
    }
    __syncthreads();
    if (tid == 0) g_candn[row] = candCnt < CAND_MAX ? candCnt : CAND_MAX;
}

// -------- final: zero row, exact fp32 rescore of candidates, scatter --------
__global__ void final_kernel(float* __restrict__ out, const int* __restrict__ kp)
{
    __shared__ float erow[DIM];
    __shared__ float cval[CAND_MAX];
    __shared__ int   cidx[CAND_MAX];

    const int row = blockIdx.x;
    const int tid = threadIdx.x;           // 256
    const int n   = g_candn[row];
    const int K1  = kp[0] + 1;

    erow[tid] = g_e[(long)row * DIM + tid];
    __syncthreads();

    for (int c = tid; c < n; c += 256) {
        int idx = g_cand[row * CAND_MAX + c];
        const float* ec = &g_e[(long)idx * DIM];
        float a = 0.f;
#pragma unroll 8
        for (int k = 0; k < DIM; ++k) a = fmaf(erow[k], ec[k], a);
        cval[c] = a;
        cidx[c] = idx;
    }
    __syncthreads();

    float4* o4 = reinterpret_cast<float4*>(out + (long)row * LDOUT);
    const float4 z = make_float4(0.f, 0.f, 0.f, 0.f);
    for (int i = tid; i < LDOUT / 4; i += 256) o4[i] = z;
    __syncthreads();

    for (int c = tid; c < n; c += 256) {
        float v = cval[c];
        int  id = cidx[c];
        int rank = 0;
        for (int o = 0; o < n; ++o) {
            float vo = cval[o];
            rank += (vo > v) || (vo == v && cidx[o] < id);
        }
        if (rank < K1) out[(long)row * LDOUT + id] = fmaxf(v, 0.f);
    }
}

// ---------------- launch ----------------------------------------------------
extern "C" void kernel_launch(void* const* d_in, const int* in_sizes, int n_in,
                              void* d_out, int out_size)
{
    const float* h  = (const float*)d_in[0];
    const float* W1 = (const float*)d_in[1];
    const float* b1 = (const float*)d_in[2];
    const float* W2 = (const float*)d_in[3];
    const float* b2 = (const float*)d_in[4];
    const int*   kp = (const int*)  d_in[5];
    float* out = (float*)d_out;

    mlp1_kernel<<<dim3(NB, 2), 256>>>(h, W1, b1);
    mlp2_kernel<<<dim3(NB, 2), 256>>>(W2, b2);
    normalize_kernel<<<NPAD, 256>>>();
    adj_hmma_kernel<<<dim3(NB, NB), 256>>>(out);
    cand_kernel<<<N_ROWS, 256>>>(out, kp);
    final_kernel<<<N_ROWS, 256>>>(out, kp);
}

// round 9
// speedup vs baseline: 1.4346x; 1.0794x over previous
#include <cuda_runtime.h>
#include <cuda_bf16.h>
#include <cstdint>

#define N_ROWS 10000
#define DIM    256
#define NB     79            // ceil(10000/128)
#define NPAD   (NB * 128)    // 10112
#define LDOUT  10000
#define CAND_MAX 2048
#define DELTA  1e-2f

// ---------------- scratch (static device globals: allocation-free) ----------
__device__ float g_x1[NPAD * DIM];
__device__ float g_e [NPAD * DIM];
__device__ __nv_bfloat16 g_ehi[NPAD * DIM];

// ================= helpers =================
__device__ __forceinline__ uint32_t smem_u32(const void* p) {
    uint32_t a;
    asm("{ .reg .u64 t; cvta.to.shared.u64 t, %1; cvt.u32.u64 %0, t; }" : "=r"(a) : "l"(p));
    return a;
}
__device__ __forceinline__ void cp16(uint32_t dst, const void* src) {
    asm volatile("cp.async.cg.shared.global [%0], [%1], 16;" :: "r"(dst), "l"(src));
}
#define CP_COMMIT() asm volatile("cp.async.commit_group;")
#define CP_WAIT0()  asm volatile("cp.async.wait_group 0;")

__device__ __forceinline__ void ldm_x4(uint32_t& r0, uint32_t& r1, uint32_t& r2, uint32_t& r3,
                                       uint32_t addr) {
    asm volatile("ldmatrix.sync.aligned.m8n8.x4.shared.b16 {%0,%1,%2,%3}, [%4];"
                 : "=r"(r0), "=r"(r1), "=r"(r2), "=r"(r3) : "r"(addr));
}
__device__ __forceinline__ void ldm_x2(uint32_t& r0, uint32_t& r1, uint32_t addr) {
    asm volatile("ldmatrix.sync.aligned.m8n8.x2.shared.b16 {%0,%1}, [%2];"
                 : "=r"(r0), "=r"(r1) : "r"(addr));
}
__device__ __forceinline__ void mma_bf16(float* c, const uint32_t* a, const uint32_t* b) {
    asm volatile("mma.sync.aligned.m16n8k16.row.col.f32.bf16.bf16.f32 "
                 "{%0,%1,%2,%3}, {%4,%5,%6,%7}, {%8,%9}, {%0,%1,%2,%3};"
                 : "+f"(c[0]), "+f"(c[1]), "+f"(c[2]), "+f"(c[3])
                 : "r"(a[0]), "r"(a[1]), "r"(a[2]), "r"(a[3]), "r"(b[0]), "r"(b[1]));
}

// ---------------- shared GEMM core: C = act(A @ W^T + bias) -----------------
template<bool RELU, bool GUARD_A>
__device__ __forceinline__ void mlp_gemm_core(const float* __restrict__ A,
                                              const float* __restrict__ W,
                                              const float* __restrict__ bias,
                                              float* __restrict__ C, int mreal)
{
    __shared__ float As[16][128];
    __shared__ float Bs[16][128];
    const int tid  = threadIdx.x;
    const int tx   = tid & 15, ty = tid >> 4;
    const int row0 = ty * 8, col0 = tx * 8;
    const int br = blockIdx.x, bc = blockIdx.y;

    float c[8][8];
#pragma unroll
    for (int i = 0; i < 8; i++)
#pragma unroll
        for (int j = 0; j < 8; j++) c[i][j] = 0.f;

    for (int k0 = 0; k0 < DIM; k0 += 16) {
#pragma unroll
        for (int l = 0; l < 2; l++) {
            int idx = tid * 2 + l;
            int r   = idx >> 2;
            int c4  = (idx & 3) * 4;
            int arow = br * 128 + r;
            float4 v;
            if (!GUARD_A || arow < mreal)
                v = *reinterpret_cast<const float4*>(&A[(long)arow * DIM + k0 + c4]);
            else
                v = make_float4(0.f, 0.f, 0.f, 0.f);
            As[c4 + 0][r] = v.x; As[c4 + 1][r] = v.y;
            As[c4 + 2][r] = v.z; As[c4 + 3][r] = v.w;
            int wrow = bc * 128 + r;
            float4 w = *reinterpret_cast<const float4*>(&W[(long)wrow * DIM + k0 + c4]);
            Bs[c4 + 0][r] = w.x; Bs[c4 + 1][r] = w.y;
            Bs[c4 + 2][r] = w.z; Bs[c4 + 3][r] = w.w;
        }
        __syncthreads();
#pragma unroll
        for (int k = 0; k < 16; k++) {
            float a[8], b[8];
            *(float4*)&a[0] = *(const float4*)&As[k][row0];
            *(float4*)&a[4] = *(const float4*)&As[k][row0 + 4];
            *(float4*)&b[0] = *(const float4*)&Bs[k][col0];
            *(float4*)&b[4] = *(const float4*)&Bs[k][col0 + 4];
#pragma unroll
            for (int i = 0; i < 8; i++)
#pragma unroll
                for (int j = 0; j < 8; j++)
                    c[i][j] = fmaf(a[i], b[j], c[i][j]);
        }
        __syncthreads();
    }
#pragma unroll
    for (int i = 0; i < 8; i++) {
        int grow = br * 128 + row0 + i;
#pragma unroll
        for (int j = 0; j < 8; j++) {
            int gcol = bc * 128 + col0 + j;
            float v = c[i][j] + bias[gcol];
            if (RELU) v = fmaxf(v, 0.f);
            C[(long)grow * DIM + gcol] = v;
        }
    }
}

__global__ void mlp1_kernel(const float* __restrict__ h,
                            const float* __restrict__ W1,
                            const float* __restrict__ b1)
{
    mlp_gemm_core<true, true>(h, W1, b1, g_x1, N_ROWS);
}

__global__ void mlp2_kernel(const float* __restrict__ W2,
                            const float* __restrict__ b2)
{
    mlp_gemm_core<false, false>(g_x1, W2, b2, g_e, N_ROWS);
}

// -------- row L2-normalize; emit fp32 e and bf16; zero pads -----------------
__global__ void normalize_kernel()
{
    const int row = blockIdx.x;
    const int tid = threadIdx.x;           // 256 == DIM
    float v = g_e[(long)row * DIM + tid];
    float s = v * v;
#pragma unroll
    for (int off = 16; off > 0; off >>= 1)
        s += __shfl_xor_sync(0xffffffffu, s, off);
    __shared__ float warpsum[8];
    if ((tid & 31) == 0) warpsum[tid >> 5] = s;
    __syncthreads();
    float tot = 0.f;
#pragma unroll
    for (int w = 0; w < 8; w++) tot += warpsum[w];
    float denom = fmaxf(sqrtf(tot), 1e-12f);
    float e = (row < N_ROWS) ? v / denom : 0.f;
    g_e[(long)row * DIM + tid] = e;
    g_ehi[(long)row * DIM + tid] = __float2bfloat16(e);
}

// ---------------- approx adj via mma.sync bf16 (symmetric) ------------------
#define KT    32
#define APAD  40                         // row pitch in bf16 elems (80 B)
#define MATB  (128 * APAD * 2)           // 10240 B per matrix buffer
#define BUFB  (2 * MATB)                 // A+B per buffer
#define NCHUNK 8                         // 256 / 32

__global__ void __launch_bounds__(256, 2) adj_hmma_kernel(float* __restrict__ out)
{
    const int bc = blockIdx.x, br = blockIdx.y;
    if (bc < br) return;

    __shared__ __align__(16) char smem_raw[2 * BUFB];   // 40960 B
    const uint32_t sb = smem_u32(smem_raw);

    const int tid  = threadIdx.x;
    const int wid  = tid >> 5, lane = tid & 31;
    const int warp_m = wid >> 2, warp_n = wid & 3;      // 2 x 4 warp grid

    float acc[4][4][4];
#pragma unroll
    for (int mi = 0; mi < 4; mi++)
#pragma unroll
        for (int ni = 0; ni < 4; ni++)
#pragma unroll
            for (int q = 0; q < 4; q++) acc[mi][ni][q] = 0.f;

    const size_t aBase = (size_t)(br * 128) * DIM;
    const size_t bBase = (size_t)(bc * 128) * DIM;

    const int u0r = tid >> 2,         u0c = (tid & 3) * 16;
    const int u1r = (tid + 256) >> 2, u1c = u0c;

    auto issue = [&](int chunk, int buf) {
        const int kk = chunk * KT;
        const char* gA = (const char*)(g_ehi + aBase + kk);
        const char* gB = (const char*)(g_ehi + bBase + kk);
        uint32_t dA = sb + buf * BUFB;
        uint32_t dB = dA + MATB;
        cp16(dA + u0r * 80 + u0c, gA + (size_t)u0r * (DIM * 2) + u0c);
        cp16(dA + u1r * 80 + u1c, gA + (size_t)u1r * (DIM * 2) + u1c);
        cp16(dB + u0r * 80 + u0c, gB + (size_t)u0r * (DIM * 2) + u0c);
        cp16(dB + u1r * 80 + u1c, gB + (size_t)u1r * (DIM * 2) + u1c);
    };

    const uint32_t aAddr0 = sb + ((warp_m * 64 + (lane & 15)) * APAD) * 2 + (lane >> 4) * 16;
    const uint32_t bAddr0 = sb + MATB + ((warp_n * 32 + (lane & 7)) * APAD) * 2
                               + ((lane >> 3) & 1) * 16;

    issue(0, 0); CP_COMMIT(); CP_WAIT0(); __syncthreads();

#pragma unroll
    for (int c = 0; c < NCHUNK; ++c) {
        const int buf = c & 1;
        if (c + 1 < NCHUNK) { issue(c + 1, buf ^ 1); CP_COMMIT(); }

        const uint32_t aB = aAddr0 + buf * BUFB;
        const uint32_t bB = bAddr0 + buf * BUFB;
#pragma unroll
        for (int ks = 0; ks < 2; ++ks) {
            uint32_t afr[4][4], bfr[4][2];
#pragma unroll
            for (int mi = 0; mi < 4; mi++)
                ldm_x4(afr[mi][0], afr[mi][1], afr[mi][2], afr[mi][3],
                       aB + mi * (16 * APAD * 2) + ks * 32);
#pragma unroll
            for (int ni = 0; ni < 4; ni++)
                ldm_x2(bfr[ni][0], bfr[ni][1],
                       bB + ni * (8 * APAD * 2) + ks * 32);
#pragma unroll
            for (int mi = 0; mi < 4; mi++)
#pragma unroll
                for (int ni = 0; ni < 4; ni++)
                    mma_bf16(acc[mi][ni], afr[mi], bfr[ni]);
        }
        if (c + 1 < NCHUNK) { CP_WAIT0(); __syncthreads(); }
    }

    // ---- direct store of upper tile ----
#pragma unroll
    for (int mi = 0; mi < 4; mi++) {
        const int r0 = br * 128 + warp_m * 64 + mi * 16 + (lane >> 2);
#pragma unroll
        for (int ni = 0; ni < 4; ni++) {
            const int gc = bc * 128 + warp_n * 32 + ni * 8 + (lane & 3) * 2;
            if (gc < N_ROWS) {
                if (r0 < N_ROWS)
                    *reinterpret_cast<float2*>(&out[(long)r0 * LDOUT + gc]) =
                        make_float2(acc[mi][ni][0], acc[mi][ni][1]);
                if (r0 + 8 < N_ROWS)
                    *reinterpret_cast<float2*>(&out[(long)(r0 + 8) * LDOUT + gc]) =
                        make_float2(acc[mi][ni][2], acc[mi][ni][3]);
            }
        }
    }

    // ---- mirrored store via smem transpose (skip diagonal) ----
    if (br != bc) {
        float* Tf = reinterpret_cast<float*>(smem_raw);   // [128 cols][68 rows]
#pragma unroll
        for (int h = 0; h < 2; ++h) {
            __syncthreads();
            if (warp_m == h) {
#pragma unroll
                for (int mi = 0; mi < 4; mi++) {
                    const int rl = mi * 16 + (lane >> 2);
#pragma unroll
                    for (int ni = 0; ni < 4; ni++) {
                        const int cl = warp_n * 32 + ni * 8 + (lane & 3) * 2;
                        Tf[cl * 68 + rl]           = acc[mi][ni][0];
                        Tf[(cl + 1) * 68 + rl]     = acc[mi][ni][1];
                        Tf[cl * 68 + rl + 8]       = acc[mi][ni][2];
                        Tf[(cl + 1) * 68 + rl + 8] = acc[mi][ni][3];
                    }
                }
            }
            __syncthreads();
#pragma unroll
            for (int p = 0; p < 8; ++p) {
                const int idx = tid + p * 256;
                const int i = idx >> 4;
                const int j = idx & 15;
                const int grow2 = bc * 128 + i;
                if (grow2 < N_ROWS) {
                    long base = (long)grow2 * LDOUT + br * 128 + h * 64 + j * 4;
                    float4 v;
                    v.x = Tf[i * 68 + j * 4 + 0];
                    v.y = Tf[i * 68 + j * 4 + 1];
                    v.z = Tf[i * 68 + j * 4 + 2];
                    v.w = Tf[i * 68 + j * 4 + 3];
                    *reinterpret_cast<float4*>(&out[base]) = v;
                }
            }
        }
    }
}

// ---- fused select: 2-level radix threshold + margin collect + exact rescore
__device__ __forceinline__ unsigned fkey(float f)
{
    unsigned u = __float_as_uint(f);
    return (u & 0x80000000u) ? ~u : (u | 0x80000000u);
}
__device__ __forceinline__ float kinv(unsigned key)
{
    unsigned u = (key & 0x80000000u) ? (key & 0x7fffffffu) : ~key;
    return __uint_as_float(u);
}

__global__ void select_kernel(float* __restrict__ out, const int* __restrict__ kp)
{
    __shared__ unsigned hist[4096];
    __shared__ unsigned chunkSum[256];
    __shared__ float erow[DIM];
    __shared__ float cval[CAND_MAX];
    __shared__ int   cidx[CAND_MAX];
    __shared__ int candCnt;
    __shared__ unsigned sh_b1, sh_r1, sh_b2;

    const int row = blockIdx.x;
    const int tid = threadIdx.x;
    float* rowp = out + (long)row * LDOUT;
    const float4* r4 = reinterpret_cast<const float4*>(rowp);
    const unsigned K1 = (unsigned)(kp[0] + 1);

    for (int i = tid; i < 4096; i += 256) hist[i] = 0;
    if (tid == 0) candCnt = 0;
    erow[tid] = g_e[(long)row * DIM + tid];
    __syncthreads();

    // ---- pass 1: top-12-bit histogram (DRAM read) ----
    for (int i = tid; i < LDOUT / 4; i += 256) {
        float4 v = r4[i];
        atomicAdd(&hist[fkey(v.x) >> 20], 1u);
        atomicAdd(&hist[fkey(v.y) >> 20], 1u);
        atomicAdd(&hist[fkey(v.z) >> 20], 1u);
        atomicAdd(&hist[fkey(v.w) >> 20], 1u);
    }
    __syncthreads();
    {
        unsigned s = 0;
#pragma unroll
        for (int b = 0; b < 16; b++) s += hist[tid * 16 + b];
        chunkSum[tid] = s;
    }
    __syncthreads();
    if (tid == 0) {
        unsigned cum = 0;
        for (int t = 255; t >= 0; --t) {
            if (cum + chunkSum[t] >= K1) {
                for (int b = t * 16 + 15; b >= t * 16; --b) {
                    unsigned hh = hist[b];
                    if (cum + hh >= K1) { sh_b1 = (unsigned)b; sh_r1 = K1 - cum; break; }
                    cum += hh;
                }
                break;
            }
            cum += chunkSum[t];
        }
    }
    __syncthreads();
    const unsigned b1 = sh_b1, r1 = sh_r1;

    // ---- pass 2: refine next 12 bits inside bin b1 (L2-resident) ----
    for (int i = tid; i < 4096; i += 256) hist[i] = 0;
    __syncthreads();
    for (int i = tid; i < LDOUT / 4; i += 256) {
        float4 v = r4[i];
        const float* pv = &v.x;
#pragma unroll
        for (int q = 0; q < 4; ++q) {
            unsigned u = fkey(pv[q]);
            if ((u >> 20) == b1) atomicAdd(&hist[(u >> 8) & 0xFFFu], 1u);
        }
    }
    __syncthreads();
    {
        unsigned s = 0;
#pragma unroll
        for (int b = 0; b < 16; b++) s += hist[tid * 16 + b];
        chunkSum[tid] = s;
    }
    __syncthreads();
    if (tid == 0) {
        unsigned cum = 0;
        sh_b2 = 0;
        for (int t = 255; t >= 0; --t) {
            if (cum + chunkSum[t] >= r1) {
                for (int b = t * 16 + 15; b >= t * 16; --b) {
                    unsigned hh = hist[b];
                    if (cum + hh >= r1) { sh_b2 = (unsigned)b; break; }
                    cum += hh;
                }
                break;
            }
            cum += chunkSum[t];
        }
    }
    __syncthreads();

    // threshold with margin (covers bf16 GEMM error, worst-case 2^-8)
    const unsigned F = (b1 << 20) | (sh_b2 << 8);
    const unsigned Tm = fkey(kinv(F) - DELTA);

    // ---- pass 3: collect candidate indices (L2-resident) ----
    for (int i = tid; i < LDOUT / 4; i += 256) {
        float4 v = r4[i];
        const float* pv = &v.x;
#pragma unroll
        for (int q = 0; q < 4; ++q) {
            if (fkey(pv[q]) >= Tm) {
                int p = atomicAdd(&candCnt, 1);
                if (p < CAND_MAX) cidx[p] = i * 4 + q;
            }
        }
    }
    __syncthreads();
    const int n = candCnt < CAND_MAX ? candCnt : CAND_MAX;

    // ---- exact fp32 rescore ----
    for (int c = tid; c < n; c += 256) {
        const float* ec = &g_e[(long)cidx[c] * DIM];
        float a = 0.f;
#pragma unroll 8
        for (int k = 0; k < DIM; ++k) a = fmaf(erow[k], ec[k], a);
        cval[c] = a;
    }
    __syncthreads();

    // ---- zero the row, then scatter kept entries ----
    float4* o4 = reinterpret_cast<float4*>(rowp);
    const float4 z = make_float4(0.f, 0.f, 0.f, 0.f);
    for (int i = tid; i < LDOUT / 4; i += 256) o4[i] = z;
    __syncthreads();

    for (int c = tid; c < n; c += 256) {
        float v = cval[c];
        int  id = cidx[c];
        int rank = 0;
        for (int o = 0; o < n; ++o) {
            float vo = cval[o];
            rank += (vo > v) || (vo == v && cidx[o] < id);
        }
        if (rank < (int)K1) rowp[id] = fmaxf(v, 0.f);
    }
}

// ---------------- launch ----------------------------------------------------
extern "C" void kernel_launch(void* const* d_in, const int* in_sizes, int n_in,
                              void* d_out, int out_size)
{
    const float* h  = (const float*)d_in[0];
    const float* W1 = (const float*)d_in[1];
    const float* b1 = (const float*)d_in[2];
    const float* W2 = (const float*)d_in[3];
    const float* b2 = (const float*)d_in[4];
    const int*   kp = (const int*)  d_in[5];
    float* out = (float*)d_out;

    mlp1_kernel<<<dim3(NB, 2), 256>>>(h, W1, b1);
    mlp2_kernel<<<dim3(NB, 2), 256>>>(W2, b2);
    normalize_kernel<<<NPAD, 256>>>();
    adj_hmma_kernel<<<dim3(NB, NB), 256>>>(out);
    select_kernel<<<N_ROWS, 256>>>(out, kp);
}